// round 14
// baseline (speedup 1.0000x reference)
#include <cuda_runtime.h>
#include <cuda_fp16.h>

#define FULLMASK 0xffffffffu
typedef unsigned int u32;

static constexpr int PHH = 72;         // fp16 tile pitch (halves), 144B rows
static constexpr int MAT_STRIDE = 4 * 8 * 32;   // uint2 per weight matrix (ks*nb*lane)

// ---- shared-memory layout (bytes) ----
static constexpr int HH_OFF   = 0;          // half[64*72] residual h (UNROTATED)
static constexpr int QH_OFF   = 9216;       // half[64*72] q -> o in place (ROTATED); xs+winf overlay at init
static constexpr int KH_OFF   = 18432;      // half[64*72] k (ROTATED); pool overlays at tail
static constexpr int VH_OFF   = 27648;      // half[64*72] v (ROTATED)
static constexpr int BB_OFF   = 36864;      // float[192] bo|ln_g|ln_b
static constexpr int PN_OFF   = 37632;      // short[32*12] pair-union neighbor ids
static constexpr int PM_OFF   = 38400;      // int[32] validity masks (m0 | m1<<16)
static constexpr int SMEM_BYTES = 38528;
static constexpr int XS_OFF   = QH_OFF;           // float[768] (init only)
static constexpr int WINF_OFF = QH_OFF + 3072;    // float[768] (init only)
static constexpr int POOL_OFF = KH_OFF;           // float[256] (tail only)

// head-slice rotation: physical col base of head hd at row r (16-half slices
// rotated per 8-row group to kill stride-8 bank aliasing of the 144B pitch)
__device__ __forceinline__ int pc0(int r, int hd) { return ((hd + (r >> 3)) & 3) << 4; }

__device__ short g_pn[32 * 12];   // pair p covers rows 2p,2p+1: union neighbor list
__device__ int   g_pm[32];        // bit j: row0 adj; bit 16+j: row1 adj
// Fragment-major packed weights; Wq pre-scaled by 0.25.
__device__ __align__(16) uint2 g_WB2[12 * MAT_STRIDE];

__global__ void prep_kernel(const int* __restrict__ adj,
                            const float* __restrict__ Wq, const float* __restrict__ Wk,
                            const float* __restrict__ Wv, const float* __restrict__ Wo) {
    if (blockIdx.x == 0) {
        int p = threadIdx.x;
        if (p < 32) {
            const int r0 = 2 * p, r1 = 2 * p + 1;
            int cnt = 0, m0 = 0, m1 = 0;
            short pn[12];
            for (int j = 0; j < 64 && cnt < 12; j++) {
                const int a0 = adj[r0 * 64 + j], a1 = adj[r1 * 64 + j];
                if (a0 | a1) {
                    pn[cnt] = (short)j;
                    if (a0) m0 |= 1 << cnt;
                    if (a1) m1 |= 1 << (16 + cnt);
                    cnt++;
                }
            }
            for (int c = cnt; c < 12; c++) pn[c] = 0;
            for (int c = 0; c < 12; c++) g_pn[p * 12 + c] = pn[c];
            g_pm[p] = m0 | m1;
        }
        return;
    }
    int m = blockIdx.x - 1;        // lay*4 + {q,k,v,o}
    int lay = m >> 2, w = m & 3;
    const float* src = (w == 0 ? Wq : w == 1 ? Wk : w == 2 ? Wv : Wo) + lay * 4096;
    const float scale = (w == 0) ? 0.25f : 1.0f;
    __half* dsth = reinterpret_cast<__half*>(g_WB2 + m * MAT_STRIDE);
    for (int i = threadIdx.x; i < 4096; i += 256) {
        int k = i >> 6, n = i & 63;
        int g = n & 7, nb = n >> 3, ks = k >> 4, kr = k & 15;
        int t = (kr & 7) >> 1;
        int slot = (kr & 1) | ((kr >> 3) << 1);
        int fidx = (ks * 8 + nb) * 32 + g * 4 + t;
        dsth[fidx * 4 + slot] = __float2half_rn(src[k * 64 + n] * scale);
    }
}

__device__ __forceinline__ void mma16816(float c[4], u32 a0, u32 a1, u32 a2, u32 a3, u32 b0, u32 b1) {
    asm volatile("mma.sync.aligned.m16n8k16.row.col.f32.f16.f16.f32 "
        "{%0,%1,%2,%3}, {%4,%5,%6,%7}, {%8,%9}, {%0,%1,%2,%3};"
        : "+f"(c[0]), "+f"(c[1]), "+f"(c[2]), "+f"(c[3])
        : "r"(a0), "r"(a1), "r"(a2), "r"(a3), "r"(b0), "r"(b1));
}

// fused QKV GEMM, 2x2 warp tiling; A from hh (unrotated), B from L2,
// C stores into ROTATED q/k/v layout.
__device__ __forceinline__ void mma_gemm3(const __half* __restrict__ A,
                                          const uint2* __restrict__ Wb,
                                          __half* __restrict__ C0, __half* __restrict__ C1,
                                          __half* __restrict__ C2, int wp, int l) {
    const int rt = (wp & 1) * 32;
    const int hd = wp >> 1;              // head / 16-col group
    const int g = l >> 2, t = l & 3;
    const int nb0 = hd * 2;
    const int lane4 = g * 4 + t;
    float acc[3][2][2][4] = {};
    const __half* ar0 = A + (rt + g) * PHH + 2 * t;
    const __half* ar1 = A + (rt + 16 + g) * PHH + 2 * t;
    #pragma unroll
    for (int ks = 0; ks < 4; ks++) {
        uint2 bf[3][2];
        #pragma unroll
        for (int m = 0; m < 3; m++)
            #pragma unroll
            for (int nt = 0; nt < 2; nt++)
                bf[m][nt] = __ldg(Wb + m * MAT_STRIDE + (ks * 8 + nb0 + nt) * 32 + lane4);
        const int k0 = 16 * ks;
        u32 a[2][4];
        a[0][0] = *reinterpret_cast<const u32*>(ar0 + k0);
        a[0][1] = *reinterpret_cast<const u32*>(ar0 + 8 * PHH + k0);
        a[0][2] = *reinterpret_cast<const u32*>(ar0 + k0 + 8);
        a[0][3] = *reinterpret_cast<const u32*>(ar0 + 8 * PHH + k0 + 8);
        a[1][0] = *reinterpret_cast<const u32*>(ar1 + k0);
        a[1][1] = *reinterpret_cast<const u32*>(ar1 + 8 * PHH + k0);
        a[1][2] = *reinterpret_cast<const u32*>(ar1 + k0 + 8);
        a[1][3] = *reinterpret_cast<const u32*>(ar1 + 8 * PHH + k0 + 8);
        #pragma unroll
        for (int m = 0; m < 3; m++) {
            #pragma unroll
            for (int nt = 0; nt < 2; nt++) {
                mma16816(acc[m][0][nt], a[0][0], a[0][1], a[0][2], a[0][3], bf[m][nt].x, bf[m][nt].y);
                mma16816(acc[m][1][nt], a[1][0], a[1][1], a[1][2], a[1][3], bf[m][nt].x, bf[m][nt].y);
            }
        }
    }
    __half* Cs[3] = {C0, C1, C2};
    #pragma unroll
    for (int m = 0; m < 3; m++) {
        #pragma unroll
        for (int rr = 0; rr < 2; rr++) {
            const int base = rt + rr * 16;            // 8-aligned row base (g=0..7)
            const int col0 = pc0(base, hd);           // rows base..base+7
            const int col1 = pc0(base + 8, hd);       // rows base+8..base+15
            #pragma unroll
            for (int nt = 0; nt < 2; nt++) {
                const int cl = nt * 8 + 2 * t;
                *reinterpret_cast<half2*>(Cs[m] + (base + g) * PHH + col0 + cl) =
                    __floats2half2_rn(acc[m][rr][nt][0], acc[m][rr][nt][1]);
                *reinterpret_cast<half2*>(Cs[m] + (base + 8 + g) * PHH + col1 + cl) =
                    __floats2half2_rn(acc[m][rr][nt][2], acc[m][rr][nt][3]);
            }
        }
    }
}

// Fused Wo-GEMM + residual + LayerNorm (warps 0..3; warp owns 16 rows x all 64 cols).
// A = o tile (ROTATED layout); hh unrotated.
__device__ __forceinline__ void mma_wo_ln(const __half* __restrict__ A,
                                          const uint2* __restrict__ Wb,
                                          __half* __restrict__ hh, const float* __restrict__ bbuf,
                                          int wp, int l) {
    const int r0 = wp * 16;
    const int g = l >> 2, t = l & 3;
    const int lane4 = g * 4 + t;
    const int rot0 = r0 >> 3;            // rows r0..r0+7
    const int rot1 = rot0 + 1;           // rows r0+8..r0+15
    float acc[8][4] = {};
    #pragma unroll
    for (int ks = 0; ks < 4; ks++) {
        uint2 bf[8];
        #pragma unroll
        for (int nt = 0; nt < 8; nt++)
            bf[nt] = __ldg(Wb + (ks * 8 + nt) * 32 + lane4);
        const int pb0 = ((ks + rot0) & 3) << 4;   // physical block of logical cols 16ks..
        const int pb1 = ((ks + rot1) & 3) << 4;
        const u32 a0 = *reinterpret_cast<const u32*>(A + (r0 + g) * PHH + pb0 + 2 * t);
        const u32 a1 = *reinterpret_cast<const u32*>(A + (r0 + 8 + g) * PHH + pb1 + 2 * t);
        const u32 a2 = *reinterpret_cast<const u32*>(A + (r0 + g) * PHH + pb0 + 8 + 2 * t);
        const u32 a3 = *reinterpret_cast<const u32*>(A + (r0 + 8 + g) * PHH + pb1 + 8 + 2 * t);
        #pragma unroll
        for (int nt = 0; nt < 8; nt++)
            mma16816(acc[nt], a0, a1, a2, a3, bf[nt].x, bf[nt].y);
    }
    #pragma unroll
    for (int nt = 0; nt < 8; nt++) {
        const int c = nt * 8 + 2 * t;
        const float2 bov = *reinterpret_cast<const float2*>(bbuf + c);
        const float2 h0 = __half22float2(*reinterpret_cast<const half2*>(hh + (r0 + g) * PHH + c));
        const float2 h1 = __half22float2(*reinterpret_cast<const half2*>(hh + (r0 + g + 8) * PHH + c));
        acc[nt][0] += bov.x + h0.x;  acc[nt][1] += bov.y + h0.y;
        acc[nt][2] += bov.x + h1.x;  acc[nt][3] += bov.y + h1.y;
    }
    float sm0 = 0.f, sq0 = 0.f, sm1 = 0.f, sq1 = 0.f;
    #pragma unroll
    for (int nt = 0; nt < 8; nt++) {
        sm0 += acc[nt][0] + acc[nt][1];
        sq0 += acc[nt][0] * acc[nt][0] + acc[nt][1] * acc[nt][1];
        sm1 += acc[nt][2] + acc[nt][3];
        sq1 += acc[nt][2] * acc[nt][2] + acc[nt][3] * acc[nt][3];
    }
    #pragma unroll
    for (int off = 1; off <= 2; off <<= 1) {
        sm0 += __shfl_xor_sync(FULLMASK, sm0, off);
        sq0 += __shfl_xor_sync(FULLMASK, sq0, off);
        sm1 += __shfl_xor_sync(FULLMASK, sm1, off);
        sq1 += __shfl_xor_sync(FULLMASK, sq1, off);
    }
    const float mu0 = sm0 * 0.015625f;
    const float mu1 = sm1 * 0.015625f;
    const float rs0 = rsqrtf(sq0 * 0.015625f - mu0 * mu0 + 1e-5f);
    const float rs1 = rsqrtf(sq1 * 0.015625f - mu1 * mu1 + 1e-5f);
    #pragma unroll
    for (int nt = 0; nt < 8; nt++) {
        const int c = nt * 8 + 2 * t;
        const float2 gv  = *reinterpret_cast<const float2*>(bbuf + 64 + c);
        const float2 bev = *reinterpret_cast<const float2*>(bbuf + 128 + c);
        *reinterpret_cast<half2*>(hh + (r0 + g) * PHH + c) =
            __floats2half2_rn((acc[nt][0] - mu0) * rs0 * gv.x + bev.x,
                              (acc[nt][1] - mu0) * rs0 * gv.y + bev.y);
        *reinterpret_cast<half2*>(hh + (r0 + g + 8) * PHH + c) =
            __floats2half2_rn((acc[nt][2] - mu1) * rs1 * gv.x + bev.x,
                              (acc[nt][3] - mu1) * rs1 * gv.y + bev.y);
    }
}

// load 8 half2 (16 halves) as raw registers
__device__ __forceinline__ void load8h2(const __half* __restrict__ p, half2* dst) {
    float4 a = *reinterpret_cast<const float4*>(p);
    float4 b = *reinterpret_cast<const float4*>(p + 8);
    const half2* ha = reinterpret_cast<const half2*>(&a);
    const half2* hb = reinterpret_cast<const half2*>(&b);
    #pragma unroll
    for (int i = 0; i < 4; i++) { dst[i] = ha[i]; dst[4 + i] = hb[i]; }
}

__global__ void __launch_bounds__(256, 3) gnn_kernel(
    const float* __restrict__ x,
    const float* __restrict__ W_in, const float* __restrict__ b_in,
    const float* __restrict__ bo,   const float* __restrict__ ln_g,
    const float* __restrict__ ln_b,
    const float* __restrict__ Wp1,  const float* __restrict__ bp1,
    const float* __restrict__ Wp2,  const float* __restrict__ bp2,
    float* __restrict__ out)
{
    extern __shared__ char sm[];
    __half* hh   = reinterpret_cast<__half*>(sm + HH_OFF);
    __half* qh   = reinterpret_cast<__half*>(sm + QH_OFF);
    __half* kh   = reinterpret_cast<__half*>(sm + KH_OFF);
    __half* vh   = reinterpret_cast<__half*>(sm + VH_OFF);
    float*  bbuf = reinterpret_cast<float*>(sm + BB_OFF);
    short*  pnS  = reinterpret_cast<short*>(sm + PN_OFF);
    int*    pmS  = reinterpret_cast<int*>(sm + PM_OFF);
    float*  xs   = reinterpret_cast<float*>(sm + XS_OFF);
    float*  winf = reinterpret_cast<float*>(sm + WINF_OFF);
    float*  pool = reinterpret_cast<float*>(sm + POOL_OFF);

    const int tid = threadIdx.x;
    const int wp  = tid >> 5;
    const int l   = tid & 31;
    const int b   = blockIdx.x;

    // ---- stage x, W_in (overlay on q tile), pair tables ----
    for (int i = tid; i < 768; i += 256) xs[i] = x[b * 768 + i];
    for (int i = tid; i < 768; i += 256) winf[i] = W_in[i];
    if (tid < 192) {
        reinterpret_cast<short*>(pnS)[2 * tid]     = g_pn[2 * tid];
        reinterpret_cast<short*>(pnS)[2 * tid + 1] = g_pn[2 * tid + 1];
    }
    if (tid >= 192 && tid < 224) pmS[tid - 192] = g_pm[tid - 192];
    __syncthreads();

    // ---- input projection: h = fp16(xs @ W_in + b_in), scalar fp32 (K=12) ----
    {
        float acc[8][2];
        const float bb0 = b_in[2 * l], bb1 = b_in[2 * l + 1];
        #pragma unroll
        for (int i = 0; i < 8; i++) { acc[i][0] = bb0; acc[i][1] = bb1; }
        #pragma unroll
        for (int kk = 0; kk < 12; kk += 4) {
            float4 hv[8];
            #pragma unroll
            for (int i = 0; i < 8; i++)
                hv[i] = *reinterpret_cast<const float4*>(xs + (8 * wp + i) * 12 + kk);
            float2 wv[4];
            #pragma unroll
            for (int t = 0; t < 4; t++)
                wv[t] = *reinterpret_cast<const float2*>(winf + (kk + t) * 64 + 2 * l);
            #pragma unroll
            for (int i = 0; i < 8; i++) {
                acc[i][0] += hv[i].x * wv[0].x;  acc[i][1] += hv[i].x * wv[0].y;
                acc[i][0] += hv[i].y * wv[1].x;  acc[i][1] += hv[i].y * wv[1].y;
                acc[i][0] += hv[i].z * wv[2].x;  acc[i][1] += hv[i].z * wv[2].y;
                acc[i][0] += hv[i].w * wv[3].x;  acc[i][1] += hv[i].w * wv[3].y;
            }
        }
        #pragma unroll
        for (int i = 0; i < 8; i++)
            *reinterpret_cast<half2*>(hh + (8 * wp + i) * PHH + 2 * l) =
                __floats2half2_rn(acc[i][0], acc[i][1]);
    }
    __syncthreads();

    for (int lay = 0; lay < 3; lay++) {
        // ---- P1: fused QKV GEMM (B from L2), rotated C stores ----
        mma_gemm3(hh, g_WB2 + lay * 4 * MAT_STRIDE, qh, kh, vh, wp, l);
        __syncthreads();

        // ---- P2: single-pass row-paired sparse attention (threads 0..127);
        //          threads 128..255 stage biases ----
        if (tid < 128) {
            const int pr = tid & 31;
            const int hd = tid >> 5;
            const int r0 = 2 * pr, r1 = r0 + 1;
            const int c0p = pc0(r0, hd);            // same for r0 and r1 (even base)
            const int pm = pmS[pr];
            half2 qa[8], qb[8];
            load8h2(qh + r0 * PHH + c0p, qa);
            load8h2(qh + r1 * PHH + c0p, qb);
            float a0[16] = {}, a1[16] = {};
            float sum0 = 0.f, sum1 = 0.f;
            #pragma unroll
            for (int j = 0; j < 12; j++) {
                const int idx = pnS[pr * 12 + j];
                const int c0k = pc0(idx, hd);
                half2 k2[8];
                load8h2(kh + idx * PHH + c0k, k2);
                half2 x0 = __hmul2(qa[0], k2[0]);
                half2 x1 = __hmul2(qa[1], k2[1]);
                half2 y0 = __hmul2(qb[0], k2[0]);
                half2 y1 = __hmul2(qb[1], k2[1]);
                x0 = __hfma2(qa[2], k2[2], x0);  y0 = __hfma2(qb[2], k2[2], y0);
                x1 = __hfma2(qa[3], k2[3], x1);  y1 = __hfma2(qb[3], k2[3], y1);
                x0 = __hfma2(qa[4], k2[4], x0);  y0 = __hfma2(qb[4], k2[4], y0);
                x1 = __hfma2(qa[5], k2[5], x1);  y1 = __hfma2(qb[5], k2[5], y1);
                x0 = __hfma2(qa[6], k2[6], x0);  y0 = __hfma2(qb[6], k2[6], y0);
                x1 = __hfma2(qa[7], k2[7], x1);  y1 = __hfma2(qb[7], k2[7], y1);
                const float2 fx0 = __half22float2(x0), fx1 = __half22float2(x1);
                const float2 fy0 = __half22float2(y0), fy1 = __half22float2(y1);
                const float sc0 = (fx0.x + fx1.x) + (fx0.y + fx1.y);
                const float sc1 = (fy0.x + fy1.x) + (fy0.y + fy1.y);
                const float ev0 = ((pm >> j) & 1)        ? __expf(sc0) : 0.f;
                const float ev1 = ((pm >> (16 + j)) & 1) ? __expf(sc1) : 0.f;
                sum0 += ev0;  sum1 += ev1;
                half2 v2[8];
                load8h2(vh + idx * PHH + c0k, v2);
                #pragma unroll
                for (int d = 0; d < 8; d++) {
                    const float2 f = __half22float2(v2[d]);
                    a0[2*d]   += ev0 * f.x;  a0[2*d+1] += ev0 * f.y;
                    a1[2*d]   += ev1 * f.x;  a1[2*d+1] += ev1 * f.y;
                }
            }
            const float inv0 = __frcp_rn(sum0);
            const float inv1 = __frcp_rn(sum1);
            u32 pk0[8], pk1[8];
            #pragma unroll
            for (int j = 0; j < 8; j++) {
                half2 h0 = __floats2half2_rn(a0[2*j] * inv0, a0[2*j+1] * inv0);
                half2 h1 = __floats2half2_rn(a1[2*j] * inv1, a1[2*j+1] * inv1);
                pk0[j] = *reinterpret_cast<u32*>(&h0);
                pk1[j] = *reinterpret_cast<u32*>(&h1);
            }
            uint4* d0 = reinterpret_cast<uint4*>(qh + r0 * PHH + c0p);
            uint4* d1 = reinterpret_cast<uint4*>(qh + r1 * PHH + c0p);
            d0[0] = make_uint4(pk0[0], pk0[1], pk0[2], pk0[3]);
            d0[1] = make_uint4(pk0[4], pk0[5], pk0[6], pk0[7]);
            d1[0] = make_uint4(pk1[0], pk1[1], pk1[2], pk1[3]);
            d1[1] = make_uint4(pk1[4], pk1[5], pk1[6], pk1[7]);
        } else {
            for (int i = tid - 128; i < 192; i += 128)
                bbuf[i] = (i < 64) ? bo[lay * 64 + i]
                        : (i < 128) ? ln_g[lay * 64 + i - 64]
                                    : ln_b[lay * 64 + i - 128];
        }
        __syncthreads();

        // ---- P3: warps 0-3 fused Wo-GEMM + residual + LN ----
        if (wp < 4)
            mma_wo_ln(qh, g_WB2 + (lay * 4 + 3) * MAT_STRIDE, hh, bbuf, wp, l);
        __syncthreads();
    }

    // ---- mean pool over nodes (pool overlays dead kh) ----
    if (tid < 64) {
        float ssum = 0.f;
        #pragma unroll 8
        for (int r = 0; r < 64; r++) ssum += __half2float(hh[r * PHH + tid]);
        pool[tid] = ssum * 0.015625f;
    }
    __syncthreads();
    // ---- MLP layer 1 (relu) ----
    if (tid < 64) {
        float a = bp1[tid];
        #pragma unroll 8
        for (int c = 0; c < 64; c++) a += pool[c] * Wp1[c * 64 + tid];
        pool[128 + tid] = fmaxf(a, 0.f);
    }
    __syncthreads();
    // ---- MLP layer 2 ----
    if (tid < 128) {
        float a = bp2[tid];
        #pragma unroll 8
        for (int j = 0; j < 64; j++) a += pool[128 + j] * Wp2[j * 128 + tid];
        out[b * 128 + tid] = a;
    }
}

extern "C" void kernel_launch(void* const* d_in, const int* in_sizes, int n_in,
                              void* d_out, int out_size) {
    const float* x    = (const float*)d_in[0];
    const int*   adj  = (const int*)  d_in[1];
    const float* W_in = (const float*)d_in[2];
    const float* b_in = (const float*)d_in[3];
    const float* Wq   = (const float*)d_in[4];
    const float* Wk   = (const float*)d_in[5];
    const float* Wv   = (const float*)d_in[6];
    const float* Wo   = (const float*)d_in[7];
    const float* bo   = (const float*)d_in[8];
    const float* ln_g = (const float*)d_in[9];
    const float* ln_b = (const float*)d_in[10];
    const float* Wp1  = (const float*)d_in[11];
    const float* bp1  = (const float*)d_in[12];
    const float* Wp2  = (const float*)d_in[13];
    const float* bp2  = (const float*)d_in[14];
    float* outp = (float*)d_out;

    prep_kernel<<<13, 256>>>(adj, Wq, Wk, Wv, Wo);
    gnn_kernel<<<8192, 256, SMEM_BYTES>>>(x, W_in, b_in, bo, ln_g, ln_b,
                                          Wp1, bp1, Wp2, bp2, outp);
}

// round 15
// speedup vs baseline: 1.0918x; 1.0918x over previous
#include <cuda_runtime.h>
#include <cuda_fp16.h>

#define FULLMASK 0xffffffffu
typedef unsigned int u32;

static constexpr int PHH = 72;         // fp16 tile pitch (halves), 144B rows
static constexpr int MAT_STRIDE = 4 * 8 * 32;   // uint2 per weight matrix (ks*nb*lane)

// ---- shared-memory layout (bytes) ----
static constexpr int HH_OFF   = 0;          // half[64*72] residual h
static constexpr int QH_OFF   = 9216;       // half[64*72] q -> o in place; xs+winf overlay at init
static constexpr int KH_OFF   = 18432;      // half[64*72] k; pool overlays at tail
static constexpr int VH_OFF   = 27648;      // half[64*72] v
static constexpr int BB_OFF   = 36864;      // float[192] bo|ln_g|ln_b
static constexpr int PN_OFF   = 37632;      // short[32*12] pair-union neighbor ids
static constexpr int PM_OFF   = 38400;      // int[32] validity masks (m0 | m1<<16)
static constexpr int SMEM_BYTES = 38528;
static constexpr int XS_OFF   = QH_OFF;           // float[768] (init only)
static constexpr int WINF_OFF = QH_OFF + 3072;    // float[768] (init only)
static constexpr int POOL_OFF = KH_OFF;           // float[256] (tail only)

__device__ short g_pn[32 * 12];   // pair p covers rows 2p,2p+1: union neighbor list
__device__ int   g_pm[32];        // bit j: row0 adj; bit 16+j: row1 adj
// Fragment-major packed weights; Wq pre-scaled by 0.25.
__device__ __align__(16) uint2 g_WB2[12 * MAT_STRIDE];

__global__ void prep_kernel(const int* __restrict__ adj,
                            const float* __restrict__ Wq, const float* __restrict__ Wk,
                            const float* __restrict__ Wv, const float* __restrict__ Wo) {
    if (blockIdx.x == 0) {
        int p = threadIdx.x;
        if (p < 32) {
            const int r0 = 2 * p, r1 = 2 * p + 1;
            int cnt = 0, m0 = 0, m1 = 0;
            short pn[12];
            for (int j = 0; j < 64 && cnt < 12; j++) {
                const int a0 = adj[r0 * 64 + j], a1 = adj[r1 * 64 + j];
                if (a0 | a1) {
                    pn[cnt] = (short)j;
                    if (a0) m0 |= 1 << cnt;
                    if (a1) m1 |= 1 << (16 + cnt);
                    cnt++;
                }
            }
            for (int c = cnt; c < 12; c++) pn[c] = 0;
            for (int c = 0; c < 12; c++) g_pn[p * 12 + c] = pn[c];
            g_pm[p] = m0 | m1;
        }
        return;
    }
    int m = blockIdx.x - 1;        // lay*4 + {q,k,v,o}
    int lay = m >> 2, w = m & 3;
    const float* src = (w == 0 ? Wq : w == 1 ? Wk : w == 2 ? Wv : Wo) + lay * 4096;
    const float scale = (w == 0) ? 0.25f : 1.0f;   // fold 1/sqrt(16) into Wq (exact)
    __half* dsth = reinterpret_cast<__half*>(g_WB2 + m * MAT_STRIDE);
    for (int i = threadIdx.x; i < 4096; i += 256) {
        int k = i >> 6, n = i & 63;
        int g = n & 7, nb = n >> 3, ks = k >> 4, kr = k & 15;
        int t = (kr & 7) >> 1;
        int slot = (kr & 1) | ((kr >> 3) << 1);
        int fidx = (ks * 8 + nb) * 32 + g * 4 + t;
        dsth[fidx * 4 + slot] = __float2half_rn(src[k * 64 + n] * scale);
    }
}

__device__ __forceinline__ void mma16816(float c[4], u32 a0, u32 a1, u32 a2, u32 a3, u32 b0, u32 b1) {
    asm volatile("mma.sync.aligned.m16n8k16.row.col.f32.f16.f16.f32 "
        "{%0,%1,%2,%3}, {%4,%5,%6,%7}, {%8,%9}, {%0,%1,%2,%3};"
        : "+f"(c[0]), "+f"(c[1]), "+f"(c[2]), "+f"(c[3])
        : "r"(a0), "r"(a1), "r"(a2), "r"(a3), "r"(b0), "r"(b1));
}

// fused QKV GEMM, 2x2 warp tiling; B operands streamed from L2 (frag-major gmem)
__device__ __forceinline__ void mma_gemm3(const __half* __restrict__ A,
                                          const uint2* __restrict__ Wb,
                                          __half* __restrict__ C0, __half* __restrict__ C1,
                                          __half* __restrict__ C2, int wp, int l) {
    const int rt = (wp & 1) * 32;
    const int cg = (wp >> 1) * 16;
    const int g = l >> 2, t = l & 3;
    const int nb0 = (wp >> 1) * 2;
    const int lane4 = g * 4 + t;
    float acc[3][2][2][4] = {};
    const __half* ar0 = A + (rt + g) * PHH + 2 * t;
    const __half* ar1 = A + (rt + 16 + g) * PHH + 2 * t;
    #pragma unroll
    for (int ks = 0; ks < 4; ks++) {
        uint2 bf[3][2];
        #pragma unroll
        for (int m = 0; m < 3; m++)
            #pragma unroll
            for (int nt = 0; nt < 2; nt++)
                bf[m][nt] = __ldg(Wb + m * MAT_STRIDE + (ks * 8 + nb0 + nt) * 32 + lane4);
        const int k0 = 16 * ks;
        u32 a[2][4];
        a[0][0] = *reinterpret_cast<const u32*>(ar0 + k0);
        a[0][1] = *reinterpret_cast<const u32*>(ar0 + 8 * PHH + k0);
        a[0][2] = *reinterpret_cast<const u32*>(ar0 + k0 + 8);
        a[0][3] = *reinterpret_cast<const u32*>(ar0 + 8 * PHH + k0 + 8);
        a[1][0] = *reinterpret_cast<const u32*>(ar1 + k0);
        a[1][1] = *reinterpret_cast<const u32*>(ar1 + 8 * PHH + k0);
        a[1][2] = *reinterpret_cast<const u32*>(ar1 + k0 + 8);
        a[1][3] = *reinterpret_cast<const u32*>(ar1 + 8 * PHH + k0 + 8);
        #pragma unroll
        for (int m = 0; m < 3; m++) {
            #pragma unroll
            for (int nt = 0; nt < 2; nt++) {
                mma16816(acc[m][0][nt], a[0][0], a[0][1], a[0][2], a[0][3], bf[m][nt].x, bf[m][nt].y);
                mma16816(acc[m][1][nt], a[1][0], a[1][1], a[1][2], a[1][3], bf[m][nt].x, bf[m][nt].y);
            }
        }
    }
    __half* Cs[3] = {C0, C1, C2};
    #pragma unroll
    for (int m = 0; m < 3; m++) {
        #pragma unroll
        for (int rr = 0; rr < 2; rr++) {
            #pragma unroll
            for (int nt = 0; nt < 2; nt++) {
                const int cc = cg + nt * 8 + 2 * t;
                const int r0 = rt + rr * 16 + g;
                *reinterpret_cast<half2*>(Cs[m] + r0 * PHH + cc) =
                    __floats2half2_rn(acc[m][rr][nt][0], acc[m][rr][nt][1]);
                *reinterpret_cast<half2*>(Cs[m] + (r0 + 8) * PHH + cc) =
                    __floats2half2_rn(acc[m][rr][nt][2], acc[m][rr][nt][3]);
            }
        }
    }
}

// Fused Wo-GEMM + residual + LayerNorm (warps 0..3; warp owns 16 rows x all 64 cols).
__device__ __forceinline__ void mma_wo_ln(const __half* __restrict__ A,
                                          const uint2* __restrict__ Wb,
                                          __half* __restrict__ hh, const float* __restrict__ bbuf,
                                          int wp, int l) {
    const int r0 = wp * 16;
    const int g = l >> 2, t = l & 3;
    const int lane4 = g * 4 + t;
    float acc[8][4] = {};
    const __half* ar = A + (r0 + g) * PHH + 2 * t;
    #pragma unroll
    for (int ks = 0; ks < 4; ks++) {
        uint2 bf[8];
        #pragma unroll
        for (int nt = 0; nt < 8; nt++)
            bf[nt] = __ldg(Wb + (ks * 8 + nt) * 32 + lane4);
        const int k0 = 16 * ks;
        const u32 a0 = *reinterpret_cast<const u32*>(ar + k0);
        const u32 a1 = *reinterpret_cast<const u32*>(ar + 8 * PHH + k0);
        const u32 a2 = *reinterpret_cast<const u32*>(ar + k0 + 8);
        const u32 a3 = *reinterpret_cast<const u32*>(ar + 8 * PHH + k0 + 8);
        #pragma unroll
        for (int nt = 0; nt < 8; nt++)
            mma16816(acc[nt], a0, a1, a2, a3, bf[nt].x, bf[nt].y);
    }
    #pragma unroll
    for (int nt = 0; nt < 8; nt++) {
        const int c = nt * 8 + 2 * t;
        const float2 bov = *reinterpret_cast<const float2*>(bbuf + c);
        const float2 h0 = __half22float2(*reinterpret_cast<const half2*>(hh + (r0 + g) * PHH + c));
        const float2 h1 = __half22float2(*reinterpret_cast<const half2*>(hh + (r0 + g + 8) * PHH + c));
        acc[nt][0] += bov.x + h0.x;  acc[nt][1] += bov.y + h0.y;
        acc[nt][2] += bov.x + h1.x;  acc[nt][3] += bov.y + h1.y;
    }
    float sm0 = 0.f, sq0 = 0.f, sm1 = 0.f, sq1 = 0.f;
    #pragma unroll
    for (int nt = 0; nt < 8; nt++) {
        sm0 += acc[nt][0] + acc[nt][1];
        sq0 += acc[nt][0] * acc[nt][0] + acc[nt][1] * acc[nt][1];
        sm1 += acc[nt][2] + acc[nt][3];
        sq1 += acc[nt][2] * acc[nt][2] + acc[nt][3] * acc[nt][3];
    }
    #pragma unroll
    for (int off = 1; off <= 2; off <<= 1) {
        sm0 += __shfl_xor_sync(FULLMASK, sm0, off);
        sq0 += __shfl_xor_sync(FULLMASK, sq0, off);
        sm1 += __shfl_xor_sync(FULLMASK, sm1, off);
        sq1 += __shfl_xor_sync(FULLMASK, sq1, off);
    }
    const float mu0 = sm0 * 0.015625f;
    const float mu1 = sm1 * 0.015625f;
    const float rs0 = rsqrtf(sq0 * 0.015625f - mu0 * mu0 + 1e-5f);
    const float rs1 = rsqrtf(sq1 * 0.015625f - mu1 * mu1 + 1e-5f);
    #pragma unroll
    for (int nt = 0; nt < 8; nt++) {
        const int c = nt * 8 + 2 * t;
        const float2 gv  = *reinterpret_cast<const float2*>(bbuf + 64 + c);
        const float2 bev = *reinterpret_cast<const float2*>(bbuf + 128 + c);
        *reinterpret_cast<half2*>(hh + (r0 + g) * PHH + c) =
            __floats2half2_rn((acc[nt][0] - mu0) * rs0 * gv.x + bev.x,
                              (acc[nt][1] - mu0) * rs0 * gv.y + bev.y);
        *reinterpret_cast<half2*>(hh + (r0 + g + 8) * PHH + c) =
            __floats2half2_rn((acc[nt][2] - mu1) * rs1 * gv.x + bev.x,
                              (acc[nt][3] - mu1) * rs1 * gv.y + bev.y);
    }
}

// load 8 half2 (16 halves) as raw registers
__device__ __forceinline__ void load8h2(const __half* __restrict__ p, half2* dst) {
    float4 a = *reinterpret_cast<const float4*>(p);
    float4 b = *reinterpret_cast<const float4*>(p + 8);
    const half2* ha = reinterpret_cast<const half2*>(&a);
    const half2* hb = reinterpret_cast<const half2*>(&b);
    #pragma unroll
    for (int i = 0; i < 4; i++) { dst[i] = ha[i]; dst[4 + i] = hb[i]; }
}

__global__ void __launch_bounds__(256, 3) gnn_kernel(
    const float* __restrict__ x,
    const float* __restrict__ W_in, const float* __restrict__ b_in,
    const float* __restrict__ bo,   const float* __restrict__ ln_g,
    const float* __restrict__ ln_b,
    const float* __restrict__ Wp1,  const float* __restrict__ bp1,
    const float* __restrict__ Wp2,  const float* __restrict__ bp2,
    float* __restrict__ out)
{
    extern __shared__ char sm[];
    __half* hh   = reinterpret_cast<__half*>(sm + HH_OFF);
    __half* qh   = reinterpret_cast<__half*>(sm + QH_OFF);   // q, then o in place
    __half* kh   = reinterpret_cast<__half*>(sm + KH_OFF);
    __half* vh   = reinterpret_cast<__half*>(sm + VH_OFF);
    float*  bbuf = reinterpret_cast<float*>(sm + BB_OFF);
    short*  pnS  = reinterpret_cast<short*>(sm + PN_OFF);
    int*    pmS  = reinterpret_cast<int*>(sm + PM_OFF);
    float*  xs   = reinterpret_cast<float*>(sm + XS_OFF);    // init overlay on qh
    float*  winf = reinterpret_cast<float*>(sm + WINF_OFF);
    float*  pool = reinterpret_cast<float*>(sm + POOL_OFF);  // tail overlay on kh

    const int tid = threadIdx.x;
    const int wp  = tid >> 5;
    const int l   = tid & 31;
    const int b   = blockIdx.x;

    // ---- stage x, W_in (overlay on q tile), pair tables ----
    for (int i = tid; i < 768; i += 256) xs[i] = x[b * 768 + i];
    for (int i = tid; i < 768; i += 256) winf[i] = W_in[i];
    if (tid < 192) {
        reinterpret_cast<short*>(pnS)[2 * tid]     = g_pn[2 * tid];
        reinterpret_cast<short*>(pnS)[2 * tid + 1] = g_pn[2 * tid + 1];
    }
    if (tid >= 192 && tid < 224) pmS[tid - 192] = g_pm[tid - 192];
    __syncthreads();

    // ---- input projection: h = fp16(xs @ W_in + b_in), scalar fp32 (K=12) ----
    {
        float acc[8][2];
        const float bb0 = b_in[2 * l], bb1 = b_in[2 * l + 1];
        #pragma unroll
        for (int i = 0; i < 8; i++) { acc[i][0] = bb0; acc[i][1] = bb1; }
        #pragma unroll
        for (int kk = 0; kk < 12; kk += 4) {
            float4 hv[8];
            #pragma unroll
            for (int i = 0; i < 8; i++)
                hv[i] = *reinterpret_cast<const float4*>(xs + (8 * wp + i) * 12 + kk);
            float2 wv[4];
            #pragma unroll
            for (int t = 0; t < 4; t++)
                wv[t] = *reinterpret_cast<const float2*>(winf + (kk + t) * 64 + 2 * l);
            #pragma unroll
            for (int i = 0; i < 8; i++) {
                acc[i][0] += hv[i].x * wv[0].x;  acc[i][1] += hv[i].x * wv[0].y;
                acc[i][0] += hv[i].y * wv[1].x;  acc[i][1] += hv[i].y * wv[1].y;
                acc[i][0] += hv[i].z * wv[2].x;  acc[i][1] += hv[i].z * wv[2].y;
                acc[i][0] += hv[i].w * wv[3].x;  acc[i][1] += hv[i].w * wv[3].y;
            }
        }
        #pragma unroll
        for (int i = 0; i < 8; i++)
            *reinterpret_cast<half2*>(hh + (8 * wp + i) * PHH + 2 * l) =
                __floats2half2_rn(acc[i][0], acc[i][1]);
    }
    __syncthreads();   // xs/winf dead; qh free for GEMM3 output

    for (int lay = 0; lay < 3; lay++) {
        // ---- P1: fused QKV GEMM (B from L2) ----
        mma_gemm3(hh, g_WB2 + lay * 4 * MAT_STRIDE, qh, kh, vh, wp, l);
        __syncthreads();

        // ---- P2: single-pass row-paired sparse attention (threads 0..127);
        //          threads 128..255 stage biases concurrently ----
        if (tid < 128) {
            const int pr = tid & 31;       // pair: rows 2pr, 2pr+1
            const int hd = tid >> 5;       // head 0..3
            const int c0 = hd * 16;
            const int r0 = 2 * pr, r1 = r0 + 1;
            const int pm = pmS[pr];
            half2 qa[8], qb[8];
            load8h2(qh + r0 * PHH + c0, qa);
            load8h2(qh + r1 * PHH + c0, qb);
            float a0[16] = {}, a1[16] = {};
            float sum0 = 0.f, sum1 = 0.f;
            #pragma unroll
            for (int j = 0; j < 12; j++) {
                const int idx = pnS[pr * 12 + j];
                half2 k2[8];
                load8h2(kh + idx * PHH + c0, k2);
                half2 x0 = __hmul2(qa[0], k2[0]);
                half2 x1 = __hmul2(qa[1], k2[1]);
                half2 y0 = __hmul2(qb[0], k2[0]);
                half2 y1 = __hmul2(qb[1], k2[1]);
                x0 = __hfma2(qa[2], k2[2], x0);  y0 = __hfma2(qb[2], k2[2], y0);
                x1 = __hfma2(qa[3], k2[3], x1);  y1 = __hfma2(qb[3], k2[3], y1);
                x0 = __hfma2(qa[4], k2[4], x0);  y0 = __hfma2(qb[4], k2[4], y0);
                x1 = __hfma2(qa[5], k2[5], x1);  y1 = __hfma2(qb[5], k2[5], y1);
                x0 = __hfma2(qa[6], k2[6], x0);  y0 = __hfma2(qb[6], k2[6], y0);
                x1 = __hfma2(qa[7], k2[7], x1);  y1 = __hfma2(qb[7], k2[7], y1);
                const float2 fx0 = __half22float2(x0), fx1 = __half22float2(x1);
                const float2 fy0 = __half22float2(y0), fy1 = __half22float2(y1);
                const float sc0 = (fx0.x + fx1.x) + (fx0.y + fx1.y);
                const float sc1 = (fy0.x + fy1.x) + (fy0.y + fy1.y);
                const float ev0 = ((pm >> j) & 1)        ? __expf(sc0) : 0.f;
                const float ev1 = ((pm >> (16 + j)) & 1) ? __expf(sc1) : 0.f;
                sum0 += ev0;  sum1 += ev1;
                half2 v2[8];
                load8h2(vh + idx * PHH + c0, v2);
                #pragma unroll
                for (int d = 0; d < 8; d++) {
                    const float2 f = __half22float2(v2[d]);
                    a0[2*d]   += ev0 * f.x;  a0[2*d+1] += ev0 * f.y;
                    a1[2*d]   += ev1 * f.x;  a1[2*d+1] += ev1 * f.y;
                }
            }
            const float inv0 = __frcp_rn(sum0);
            const float inv1 = __frcp_rn(sum1);
            u32 pk0[8], pk1[8];
            #pragma unroll
            for (int j = 0; j < 8; j++) {
                half2 h0 = __floats2half2_rn(a0[2*j] * inv0, a0[2*j+1] * inv0);
                half2 h1 = __floats2half2_rn(a1[2*j] * inv1, a1[2*j+1] * inv1);
                pk0[j] = *reinterpret_cast<u32*>(&h0);
                pk1[j] = *reinterpret_cast<u32*>(&h1);
            }
            uint4* d0 = reinterpret_cast<uint4*>(qh + r0 * PHH + c0);
            uint4* d1 = reinterpret_cast<uint4*>(qh + r1 * PHH + c0);
            d0[0] = make_uint4(pk0[0], pk0[1], pk0[2], pk0[3]);
            d0[1] = make_uint4(pk0[4], pk0[5], pk0[6], pk0[7]);
            d1[0] = make_uint4(pk1[0], pk1[1], pk1[2], pk1[3]);
            d1[1] = make_uint4(pk1[4], pk1[5], pk1[6], pk1[7]);
        } else {
            for (int i = tid - 128; i < 192; i += 128)
                bbuf[i] = (i < 64) ? bo[lay * 64 + i]
                        : (i < 128) ? ln_g[lay * 64 + i - 64]
                                    : ln_b[lay * 64 + i - 128];
        }
        __syncthreads();

        // ---- P3: warps 0-3 fused Wo-GEMM + residual + LN (W from L2) ----
        if (wp < 4)
            mma_wo_ln(qh, g_WB2 + (lay * 4 + 3) * MAT_STRIDE, hh, bbuf, wp, l);
        __syncthreads();
    }

    // ---- mean pool over nodes (pool overlays dead kh) ----
    if (tid < 64) {
        float ssum = 0.f;
        #pragma unroll 8
        for (int r = 0; r < 64; r++) ssum += __half2float(hh[r * PHH + tid]);
        pool[tid] = ssum * 0.015625f;
    }
    __syncthreads();
    // ---- MLP layer 1 (relu) ----
    if (tid < 64) {
        float a = bp1[tid];
        #pragma unroll 8
        for (int c = 0; c < 64; c++) a += pool[c] * Wp1[c * 64 + tid];
        pool[128 + tid] = fmaxf(a, 0.f);
    }
    __syncthreads();
    // ---- MLP layer 2 ----
    if (tid < 128) {
        float a = bp2[tid];
        #pragma unroll 8
        for (int j = 0; j < 64; j++) a += pool[128 + j] * Wp2[j * 128 + tid];
        out[b * 128 + tid] = a;
    }
}

extern "C" void kernel_launch(void* const* d_in, const int* in_sizes, int n_in,
                              void* d_out, int out_size) {
    const float* x    = (const float*)d_in[0];
    const int*   adj  = (const int*)  d_in[1];
    const float* W_in = (const float*)d_in[2];
    const float* b_in = (const float*)d_in[3];
    const float* Wq   = (const float*)d_in[4];
    const float* Wk   = (const float*)d_in[5];
    const float* Wv   = (const float*)d_in[6];
    const float* Wo   = (const float*)d_in[7];
    const float* bo   = (const float*)d_in[8];
    const float* ln_g = (const float*)d_in[9];
    const float* ln_b = (const float*)d_in[10];
    const float* Wp1  = (const float*)d_in[11];
    const float* bp1  = (const float*)d_in[12];
    const float* Wp2  = (const float*)d_in[13];
    const float* bp2  = (const float*)d_in[14];
    float* outp = (float*)d_out;

    prep_kernel<<<13, 256>>>(adj, Wq, Wk, Wv, Wo);
    gnn_kernel<<<8192, 256, SMEM_BYTES>>>(x, W_in, b_in, bo, ln_g, ln_b,
                                          Wp1, bp1, Wp2, bp2, outp);
}